// round 12
// baseline (speedup 1.0000x reference)
#include <cuda_runtime.h>
#include <math.h>

// Problem constants (fixed by setup_inputs)
#define T   64
#define NS  75
#define NW  5
#define NN  375   // NS*NW
#define DD  4096
#define NQ  150
#define SIGMA_C 0.1f
#define CREG    0.1f
#define MAXIT   15

// ---------------- device scratch (no allocations allowed) ----------------
__device__ float g_K[T][NS][NS];          // Gram per task
__device__ float g_Kpart[4][T][NS][NS];   // split-K partials
__device__ float g_Minv[T][NW][NS][NS];   // per-way inverse of (K+I+diag(Dw))
__device__ float g_z[T][NN], g_s[T][NN], g_lam[T][NN];
__device__ float g_e[T][NN], g_h[T][NN];
__device__ float g_r1[T][NN], g_Dv[T][NN], g_rs[T][NN], g_u[T][NN];
__device__ float g_nu[T][NS], g_ra[T][NS];
__device__ float g_mu[T];
__device__ float g_W[T][NW][DD];

// ---------------- Gram: K[t] = S_t S_t^T, split-K over 4 chunks ----------------
__global__ __launch_bounds__(256) void gram_kernel(const float* __restrict__ sup) {
    int c = blockIdx.x, t = blockIdx.y;
    int k0base = c * 1024;
    __shared__ float As[16][80];
    int tx = threadIdx.x % 16, ty = threadIdx.x / 16;
    int kk = tx, rr = ty;
    float acc[5][5];
#pragma unroll
    for (int a = 0; a < 5; a++)
#pragma unroll
        for (int b = 0; b < 5; b++) acc[a][b] = 0.f;
    const float* Sp = sup + (size_t)t * NS * DD;
    for (int kt = 0; kt < 64; kt++) {
        int k0 = k0base + kt * 16;
        __syncthreads();
#pragma unroll
        for (int rb = 0; rb < 80; rb += 16) {
            int r = rb + rr;
            As[kk][r] = (r < NS) ? Sp[(size_t)r * DD + k0 + kk] : 0.f;
        }
        __syncthreads();
#pragma unroll
        for (int k = 0; k < 16; k++) {
            float a[5], b[5];
#pragma unroll
            for (int i = 0; i < 5; i++) a[i] = As[k][ty * 5 + i];
#pragma unroll
            for (int j = 0; j < 5; j++) b[j] = As[k][tx * 5 + j];
#pragma unroll
            for (int i = 0; i < 5; i++)
#pragma unroll
                for (int j = 0; j < 5; j++) acc[i][j] += a[i] * b[j];
        }
    }
#pragma unroll
    for (int i = 0; i < 5; i++) {
        int r = ty * 5 + i; if (r >= NS) continue;
#pragma unroll
        for (int j = 0; j < 5; j++) {
            int cc = tx * 5 + j; if (cc >= NS) continue;
            g_Kpart[c][t][r][cc] = acc[i][j];
        }
    }
}

__global__ void gram_reduce() {
    int idx = blockIdx.x * 256 + threadIdx.x;
    if (idx < T * NS * NS) {
        const float* p = (const float*)g_Kpart;
        float v = 0.f;
#pragma unroll
        for (int c = 0; c < 4; c++) v += p[c * T * NS * NS + idx];
        ((float*)g_K)[idx] = v;
    }
}

// ---------------- init state ----------------
__global__ void setup_kernel(const int* __restrict__ labels) {
    int t = blockIdx.x, tid = threadIdx.x;
    if (tid < NN) {
        int i = tid / NW, w = tid % NW;
        float y = (labels[t * NS + i] == w) ? 1.f : 0.f;
        g_e[t][tid] = -y;
        g_h[t][tid] = CREG * y;
        g_z[t][tid] = 0.f;
        g_s[t][tid] = 1.f;
        g_lam[t][tid] = 1.f;
    }
    if (tid < NS) g_nu[t][tid] = 0.f;
}

// ---------------- residuals: rz, rs, ra, mu, r1, D ----------------
__global__ __launch_bounds__(384) void resid_kernel() {
    int t = blockIdx.x, tid = threadIdx.x;
    __shared__ float Zs[NN];
    __shared__ float red[12];
    __shared__ float smu;
    float z = 0.f, s = 1.f, lam = 1.f, e = 0.f, h = 0.f;
    if (tid < NN) {
        z = g_z[t][tid]; Zs[tid] = z;
        s = g_s[t][tid]; lam = g_lam[t][tid];
        e = g_e[t][tid]; h = g_h[t][tid];
    }
    __syncthreads();
    // mu = mean(lam*s)
    float ls = (tid < NN) ? lam * s : 0.f;
#pragma unroll
    for (int o = 16; o > 0; o >>= 1) ls += __shfl_down_sync(0xffffffffu, ls, o);
    if ((tid & 31) == 0) red[tid >> 5] = ls;
    __syncthreads();
    if (tid == 0) {
        float sum = 0.f;
        for (int wi = 0; wi < 12; wi++) sum += red[wi];
        float mu = sum / (float)NN;
        g_mu[t] = mu; smu = mu;
    }
    __syncthreads();
    float mu = smu;
    if (tid < NN) {
        int i = tid / NW, w = tid % NW;
        const float* Krow = &g_K[t][i][0];
        float kz = 0.f;
        for (int j = 0; j < NS; j++) kz += Krow[j] * Zs[j * NW + w];
        float rz = kz + z + e + lam + g_nu[t][i];
        float rs = z + s - h;
        float r1 = -rz - (lam * rs - lam * s + SIGMA_C * mu) / s;
        g_rs[t][tid] = rs;
        g_r1[t][tid] = r1;
        g_Dv[t][tid] = lam / s;
    }
    if (tid < NS) {
        float ra = 0.f;
#pragma unroll
        for (int w = 0; w < NW; w++) ra += Zs[tid * NW + w];
        g_ra[t][tid] = ra;
    }
}

// ---------------- per (task,way): M = K+I+diag(Dw), Cholesky, invert, u = Minv*r1_w ----------------
__global__ __launch_bounds__(256) void factor_kernel() {
    int w = blockIdx.x, t = blockIdx.y, tid = threadIdx.x;
    __shared__ float M[NS][NS + 1];
    __shared__ float X[NS][NS + 1];
    __shared__ float r1w[NS];
    for (int idx = tid; idx < NS * NS; idx += 256) {
        int i = idx / NS, j = idx % NS;
        float v = g_K[t][i][j];
        if (i == j) v += 1.f + g_Dv[t][i * NW + w];
        M[i][j] = v;
        X[i][j] = (i == j) ? 1.f : 0.f;
    }
    for (int j = tid; j < NS; j += 256) r1w[j] = g_r1[t][j * NW + w];
    __syncthreads();
    // Cholesky (lower, in place)
    for (int k = 0; k < NS; k++) {
        if (tid == 0) M[k][k] = sqrtf(M[k][k]);
        __syncthreads();
        float invd = 1.f / M[k][k];
        for (int i = k + 1 + tid; i < NS; i += 256) M[i][k] *= invd;
        __syncthreads();
        int nr = NS - 1 - k;
        for (int idx = tid; idx < nr * nr; idx += 256) {
            int i = k + 1 + idx / nr, j = k + 1 + idx % nr;
            if (j <= i) M[i][j] -= M[i][k] * M[j][k];
        }
        __syncthreads();
    }
    // forward: L Y = I  (column sweep)
    for (int r = 0; r < NS; r++) {
        float invd = 1.f / M[r][r];
        for (int c = tid; c < NS; c += 256) X[r][c] *= invd;
        __syncthreads();
        int nr = NS - 1 - r;
        for (int idx = tid; idx < nr * NS; idx += 256) {
            int i = r + 1 + idx / NS, c = idx % NS;
            X[i][c] -= M[i][r] * X[r][c];
        }
        __syncthreads();
    }
    // backward: L^T X = Y
    for (int r = NS - 1; r >= 0; r--) {
        float invd = 1.f / M[r][r];
        for (int c = tid; c < NS; c += 256) X[r][c] *= invd;
        __syncthreads();
        for (int idx = tid; idx < r * NS; idx += 256) {
            int i = idx / NS, c = idx % NS;
            X[i][c] -= M[r][i] * X[r][c];
        }
        __syncthreads();
    }
    // write Minv + u
    for (int idx = tid; idx < NS * NS; idx += 256)
        g_Minv[t][w][idx / NS][idx % NS] = X[idx / NS][idx % NS];
    for (int i = tid; i < NS; i += 256) {
        float acc = 0.f;
        for (int j = 0; j < NS; j++) acc += X[i][j] * r1w[j];
        g_u[t][i * NW + w] = acc;
    }
}

// ---------------- per task: Schur solve for dnu, dz, step length, state update ----------------
__global__ __launch_bounds__(384) void schur_kernel() {
    int t = blockIdx.x, tid = threadIdx.x;
    __shared__ float S[NS][NS + 1];
    __shared__ float rhs[NS];
    __shared__ float us[NN];
    __shared__ float red[12];
    __shared__ float salpha;
    for (int idx = tid; idx < NS * NS; idx += 384) {
        int i = idx / NS, j = idx % NS;
        float acc = 0.f;
#pragma unroll
        for (int w = 0; w < NW; w++) acc += g_Minv[t][w][i][j];
        S[i][j] = acc;
    }
    if (tid < NN) us[tid] = g_u[t][tid];
    __syncthreads();
    if (tid < NS) {
        float acc = g_ra[t][tid];
#pragma unroll
        for (int w = 0; w < NW; w++) acc += us[tid * NW + w];
        rhs[tid] = acc;
    }
    __syncthreads();
    // Cholesky on S
    for (int k = 0; k < NS; k++) {
        if (tid == 0) S[k][k] = sqrtf(S[k][k]);
        __syncthreads();
        float invd = 1.f / S[k][k];
        for (int i = k + 1 + tid; i < NS; i += 384) S[i][k] *= invd;
        __syncthreads();
        int nr = NS - 1 - k;
        for (int idx = tid; idx < nr * nr; idx += 384) {
            int i = k + 1 + idx / nr, j = k + 1 + idx % nr;
            if (j <= i) S[i][j] -= S[i][k] * S[j][k];
        }
        __syncthreads();
    }
    // forward L y = rhs
    for (int r = 0; r < NS; r++) {
        if (tid == 0) rhs[r] /= S[r][r];
        __syncthreads();
        float yr = rhs[r];
        for (int i = r + 1 + tid; i < NS; i += 384) rhs[i] -= S[i][r] * yr;
        __syncthreads();
    }
    // backward L^T dnu = y
    for (int r = NS - 1; r >= 0; r--) {
        if (tid == 0) rhs[r] /= S[r][r];
        __syncthreads();
        float yr = rhs[r];
        for (int i = tid; i < r; i += 384) rhs[i] -= S[r][i] * yr;
        __syncthreads();
    }
    // rhs == dnu now. dz_w = u_w - Minv_w * dnu
    float dz = 0.f, ds = 0.f, dlam = 0.f, rat = INFINITY;
    float z = 0.f, s = 1.f, lam = 1.f;
    if (tid < NN) {
        int i = tid / NW, w = tid % NW;
        float acc = us[tid];
        const float* Mi = &g_Minv[t][w][i][0];
        for (int j = 0; j < NS; j++) acc -= Mi[j] * rhs[j];
        dz = acc;
        z = g_z[t][tid]; s = g_s[t][tid]; lam = g_lam[t][tid];
        float rsv = g_rs[t][tid];
        float mu = g_mu[t];
        ds = -rsv - dz;
        dlam = (lam * dz + lam * rsv - lam * s + SIGMA_C * mu) / s;
        float ra1 = (ds   < 0.f) ? (-s   / ds)   : INFINITY;
        float ra2 = (dlam < 0.f) ? (-lam / dlam) : INFINITY;
        rat = fminf(ra1, ra2);
    }
#pragma unroll
    for (int o = 16; o > 0; o >>= 1) rat = fminf(rat, __shfl_down_sync(0xffffffffu, rat, o));
    if ((tid & 31) == 0) red[tid >> 5] = rat;
    __syncthreads();
    if (tid == 0) {
        float m = red[0];
        for (int wi = 1; wi < 12; wi++) m = fminf(m, red[wi]);
        salpha = fminf(1.f, 0.99f * m);
    }
    __syncthreads();
    float alpha = salpha;
    if (tid < NN) {
        g_z[t][tid]   = z   + alpha * dz;
        g_s[t][tid]   = s   + alpha * ds;
        g_lam[t][tid] = lam + alpha * dlam;
    }
    if (tid < NS) g_nu[t][tid] += alpha * rhs[tid];
}

// ---------------- W[t,w,d] = sum_n sup[t,n,d] * z[t,n*NW+w] ----------------
__global__ __launch_bounds__(256) void wproj_kernel(const float* __restrict__ sup) {
    int t = blockIdx.y;
    int d = blockIdx.x * 256 + threadIdx.x;
    __shared__ float zs[NN];
    for (int idx = threadIdx.x; idx < NN; idx += 256) zs[idx] = g_z[t][idx];
    __syncthreads();
    float acc[NW] = {0.f, 0.f, 0.f, 0.f, 0.f};
    const float* Sp = sup + (size_t)t * NS * DD + d;
    for (int n = 0; n < NS; n++) {
        float sv = Sp[(size_t)n * DD];
#pragma unroll
        for (int w = 0; w < NW; w++) acc[w] += sv * zs[n * NW + w];
    }
#pragma unroll
    for (int w = 0; w < NW; w++) g_W[t][w][d] = acc[w];
}

// ---------------- logits[t,q,w] = sum_d query[t,q,d] * W[t,w,d] ----------------
#define QT 10
__global__ __launch_bounds__(256) void logits_kernel(const float* __restrict__ query,
                                                     float* __restrict__ out) {
    int t = blockIdx.y;
    int q0 = blockIdx.x * QT;
    int tid = threadIdx.x;
    float acc[QT][NW];
#pragma unroll
    for (int q = 0; q < QT; q++)
#pragma unroll
        for (int w = 0; w < NW; w++) acc[q][w] = 0.f;
    const float* Qp = query + ((size_t)t * NQ + q0) * DD;
    for (int d = tid; d < DD; d += 256) {
        float wv[NW];
#pragma unroll
        for (int w = 0; w < NW; w++) wv[w] = g_W[t][w][d];
#pragma unroll
        for (int q = 0; q < QT; q++) {
            float qv = Qp[(size_t)q * DD + d];
#pragma unroll
            for (int w = 0; w < NW; w++) acc[q][w] += qv * wv[w];
        }
    }
#pragma unroll
    for (int q = 0; q < QT; q++)
#pragma unroll
        for (int w = 0; w < NW; w++)
#pragma unroll
            for (int o = 16; o > 0; o >>= 1)
                acc[q][w] += __shfl_down_sync(0xffffffffu, acc[q][w], o);
    __shared__ float part[8][QT * NW];
    int lane = tid & 31, warp = tid >> 5;
    if (lane == 0) {
#pragma unroll
        for (int q = 0; q < QT; q++)
#pragma unroll
            for (int w = 0; w < NW; w++) part[warp][q * NW + w] = acc[q][w];
    }
    __syncthreads();
    if (tid < QT * NW) {
        float v = 0.f;
#pragma unroll
        for (int wp = 0; wp < 8; wp++) v += part[wp][tid];
        int q = tid / NW, w = tid % NW;
        out[((size_t)t * NQ + q0 + q) * NW + w] = v;
    }
}

// ---------------- host ----------------
extern "C" void kernel_launch(void* const* d_in, const int* in_sizes, int n_in,
                              void* d_out, int out_size) {
    const float* query  = (const float*)d_in[0];
    const float* sup    = (const float*)d_in[1];
    const int*   labels = (const int*)d_in[2];
    (void)in_sizes; (void)n_in; (void)out_size;

    gram_kernel<<<dim3(4, T), 256>>>(sup);
    gram_reduce<<<(T * NS * NS + 255) / 256, 256>>>();
    setup_kernel<<<T, 384>>>(labels);
    for (int it = 0; it < MAXIT; it++) {
        resid_kernel<<<T, 384>>>();
        factor_kernel<<<dim3(NW, T), 256>>>();
        schur_kernel<<<T, 384>>>();
    }
    wproj_kernel<<<dim3(DD / 256, T), 256>>>(sup);
    logits_kernel<<<dim3(NQ / QT, T), 256>>>(query, (float*)d_out);
}

// round 13
// speedup vs baseline: 1.0015x; 1.0015x over previous
#include <cuda_runtime.h>
#include <math.h>

// Problem constants (fixed by setup_inputs)
#define T   64
#define NS  75
#define NW  5
#define NN  375   // NS*NW
#define DD  4096
#define NQ  150
#define SIGMA_C 0.1f
#define CREG    0.1f
#define MAXIT   15

// ---------------- device scratch (no allocations allowed) ----------------
__device__ float g_K[T][NS][NS];          // Gram per task
__device__ float g_Kpart[4][T][NS][NS];   // split-K partials
__device__ float g_Minv[T][NW][NS][NS];   // per-way inverse of (K+I+diag(Dw))
__device__ float g_z[T][NN], g_s[T][NN], g_lam[T][NN];
__device__ float g_e[T][NN], g_h[T][NN];
__device__ float g_r1[T][NN], g_Dv[T][NN], g_rs[T][NN], g_u[T][NN];
__device__ float g_nu[T][NS], g_ra[T][NS];
__device__ float g_mu[T];
__device__ float g_W[T][NW][DD];

// ---------------- Gram: K[t] = S_t S_t^T, split-K over 4 chunks ----------------
__global__ __launch_bounds__(256) void gram_kernel(const float* __restrict__ sup) {
    int c = blockIdx.x, t = blockIdx.y;
    int k0base = c * 1024;
    __shared__ float As[16][80];
    int tx = threadIdx.x % 16, ty = threadIdx.x / 16;
    int kk = tx, rr = ty;
    float acc[5][5];
#pragma unroll
    for (int a = 0; a < 5; a++)
#pragma unroll
        for (int b = 0; b < 5; b++) acc[a][b] = 0.f;
    const float* Sp = sup + (size_t)t * NS * DD;
    for (int kt = 0; kt < 64; kt++) {
        int k0 = k0base + kt * 16;
        __syncthreads();
#pragma unroll
        for (int rb = 0; rb < 80; rb += 16) {
            int r = rb + rr;
            As[kk][r] = (r < NS) ? Sp[(size_t)r * DD + k0 + kk] : 0.f;
        }
        __syncthreads();
#pragma unroll
        for (int k = 0; k < 16; k++) {
            float a[5], b[5];
#pragma unroll
            for (int i = 0; i < 5; i++) a[i] = As[k][ty * 5 + i];
#pragma unroll
            for (int j = 0; j < 5; j++) b[j] = As[k][tx * 5 + j];
#pragma unroll
            for (int i = 0; i < 5; i++)
#pragma unroll
                for (int j = 0; j < 5; j++) acc[i][j] += a[i] * b[j];
        }
    }
#pragma unroll
    for (int i = 0; i < 5; i++) {
        int r = ty * 5 + i; if (r >= NS) continue;
#pragma unroll
        for (int j = 0; j < 5; j++) {
            int cc = tx * 5 + j; if (cc >= NS) continue;
            g_Kpart[c][t][r][cc] = acc[i][j];
        }
    }
}

__global__ void gram_reduce() {
    int idx = blockIdx.x * 256 + threadIdx.x;
    if (idx < T * NS * NS) {
        const float* p = (const float*)g_Kpart;
        float v = 0.f;
#pragma unroll
        for (int c = 0; c < 4; c++) v += p[c * T * NS * NS + idx];
        ((float*)g_K)[idx] = v;
    }
}

// ---------------- init state ----------------
__global__ void setup_kernel(const int* __restrict__ labels) {
    int t = blockIdx.x, tid = threadIdx.x;
    if (tid < NN) {
        int i = tid / NW, w = tid % NW;
        float y = (labels[t * NS + i] == w) ? 1.f : 0.f;
        g_e[t][tid] = -y;
        g_h[t][tid] = CREG * y;
        g_z[t][tid] = 0.f;
        g_s[t][tid] = 1.f;
        g_lam[t][tid] = 1.f;
    }
    if (tid < NS) g_nu[t][tid] = 0.f;
}

// ---------------- residuals: rz, rs, ra, mu, r1, D ----------------
__global__ __launch_bounds__(384) void resid_kernel() {
    int t = blockIdx.x, tid = threadIdx.x;
    __shared__ float Zs[NN];
    __shared__ float red[12];
    __shared__ float smu;
    float z = 0.f, s = 1.f, lam = 1.f, e = 0.f, h = 0.f;
    if (tid < NN) {
        z = g_z[t][tid]; Zs[tid] = z;
        s = g_s[t][tid]; lam = g_lam[t][tid];
        e = g_e[t][tid]; h = g_h[t][tid];
    }
    __syncthreads();
    // mu = mean(lam*s)
    float ls = (tid < NN) ? lam * s : 0.f;
#pragma unroll
    for (int o = 16; o > 0; o >>= 1) ls += __shfl_down_sync(0xffffffffu, ls, o);
    if ((tid & 31) == 0) red[tid >> 5] = ls;
    __syncthreads();
    if (tid == 0) {
        float sum = 0.f;
        for (int wi = 0; wi < 12; wi++) sum += red[wi];
        float mu = sum / (float)NN;
        g_mu[t] = mu; smu = mu;
    }
    __syncthreads();
    float mu = smu;
    if (tid < NN) {
        int i = tid / NW, w = tid % NW;
        const float* Krow = &g_K[t][i][0];
        float kz = 0.f;
        for (int j = 0; j < NS; j++) kz += Krow[j] * Zs[j * NW + w];
        float rz = kz + z + e + lam + g_nu[t][i];
        float rs = z + s - h;
        float r1 = -rz - (lam * rs - lam * s + SIGMA_C * mu) / s;
        g_rs[t][tid] = rs;
        g_r1[t][tid] = r1;
        g_Dv[t][tid] = lam / s;
    }
    if (tid < NS) {
        float ra = 0.f;
#pragma unroll
        for (int w = 0; w < NW; w++) ra += Zs[tid * NW + w];
        g_ra[t][tid] = ra;
    }
}

// ---------------- per (task,way): M = K+I+diag(Dw), Cholesky, invert, u = Minv*r1_w ----------------
__global__ __launch_bounds__(256) void factor_kernel() {
    int w = blockIdx.x, t = blockIdx.y, tid = threadIdx.x;
    __shared__ float M[NS][NS + 1];
    __shared__ float X[NS][NS + 1];
    __shared__ float r1w[NS];
    for (int idx = tid; idx < NS * NS; idx += 256) {
        int i = idx / NS, j = idx % NS;
        float v = g_K[t][i][j];
        if (i == j) v += 1.f + g_Dv[t][i * NW + w];
        M[i][j] = v;
        X[i][j] = (i == j) ? 1.f : 0.f;
    }
    for (int j = tid; j < NS; j += 256) r1w[j] = g_r1[t][j * NW + w];
    __syncthreads();
    // Cholesky (lower, in place)
    for (int k = 0; k < NS; k++) {
        if (tid == 0) M[k][k] = sqrtf(M[k][k]);
        __syncthreads();
        float invd = 1.f / M[k][k];
        for (int i = k + 1 + tid; i < NS; i += 256) M[i][k] *= invd;
        __syncthreads();
        int nr = NS - 1 - k;
        for (int idx = tid; idx < nr * nr; idx += 256) {
            int i = k + 1 + idx / nr, j = k + 1 + idx % nr;
            if (j <= i) M[i][j] -= M[i][k] * M[j][k];
        }
        __syncthreads();
    }
    // forward: L Y = I  (column sweep)
    for (int r = 0; r < NS; r++) {
        float invd = 1.f / M[r][r];
        for (int c = tid; c < NS; c += 256) X[r][c] *= invd;
        __syncthreads();
        int nr = NS - 1 - r;
        for (int idx = tid; idx < nr * NS; idx += 256) {
            int i = r + 1 + idx / NS, c = idx % NS;
            X[i][c] -= M[i][r] * X[r][c];
        }
        __syncthreads();
    }
    // backward: L^T X = Y
    for (int r = NS - 1; r >= 0; r--) {
        float invd = 1.f / M[r][r];
        for (int c = tid; c < NS; c += 256) X[r][c] *= invd;
        __syncthreads();
        for (int idx = tid; idx < r * NS; idx += 256) {
            int i = idx / NS, c = idx % NS;
            X[i][c] -= M[r][i] * X[r][c];
        }
        __syncthreads();
    }
    // write Minv + u
    for (int idx = tid; idx < NS * NS; idx += 256)
        g_Minv[t][w][idx / NS][idx % NS] = X[idx / NS][idx % NS];
    for (int i = tid; i < NS; i += 256) {
        float acc = 0.f;
        for (int j = 0; j < NS; j++) acc += X[i][j] * r1w[j];
        g_u[t][i * NW + w] = acc;
    }
}

// ---------------- per task: Schur solve for dnu, dz, step length, state update ----------------
__global__ __launch_bounds__(384) void schur_kernel() {
    int t = blockIdx.x, tid = threadIdx.x;
    __shared__ float S[NS][NS + 1];
    __shared__ float rhs[NS];
    __shared__ float us[NN];
    __shared__ float red[12];
    __shared__ float salpha;
    for (int idx = tid; idx < NS * NS; idx += 384) {
        int i = idx / NS, j = idx % NS;
        float acc = 0.f;
#pragma unroll
        for (int w = 0; w < NW; w++) acc += g_Minv[t][w][i][j];
        S[i][j] = acc;
    }
    if (tid < NN) us[tid] = g_u[t][tid];
    __syncthreads();
    if (tid < NS) {
        float acc = g_ra[t][tid];
#pragma unroll
        for (int w = 0; w < NW; w++) acc += us[tid * NW + w];
        rhs[tid] = acc;
    }
    __syncthreads();
    // Cholesky on S
    for (int k = 0; k < NS; k++) {
        if (tid == 0) S[k][k] = sqrtf(S[k][k]);
        __syncthreads();
        float invd = 1.f / S[k][k];
        for (int i = k + 1 + tid; i < NS; i += 384) S[i][k] *= invd;
        __syncthreads();
        int nr = NS - 1 - k;
        for (int idx = tid; idx < nr * nr; idx += 384) {
            int i = k + 1 + idx / nr, j = k + 1 + idx % nr;
            if (j <= i) S[i][j] -= S[i][k] * S[j][k];
        }
        __syncthreads();
    }
    // forward L y = rhs
    for (int r = 0; r < NS; r++) {
        if (tid == 0) rhs[r] /= S[r][r];
        __syncthreads();
        float yr = rhs[r];
        for (int i = r + 1 + tid; i < NS; i += 384) rhs[i] -= S[i][r] * yr;
        __syncthreads();
    }
    // backward L^T dnu = y
    for (int r = NS - 1; r >= 0; r--) {
        if (tid == 0) rhs[r] /= S[r][r];
        __syncthreads();
        float yr = rhs[r];
        for (int i = tid; i < r; i += 384) rhs[i] -= S[r][i] * yr;
        __syncthreads();
    }
    // rhs == dnu now. dz_w = u_w - Minv_w * dnu
    float dz = 0.f, ds = 0.f, dlam = 0.f, rat = INFINITY;
    float z = 0.f, s = 1.f, lam = 1.f;
    if (tid < NN) {
        int i = tid / NW, w = tid % NW;
        float acc = us[tid];
        const float* Mi = &g_Minv[t][w][i][0];
        for (int j = 0; j < NS; j++) acc -= Mi[j] * rhs[j];
        dz = acc;
        z = g_z[t][tid]; s = g_s[t][tid]; lam = g_lam[t][tid];
        float rsv = g_rs[t][tid];
        float mu = g_mu[t];
        ds = -rsv - dz;
        dlam = (lam * dz + lam * rsv - lam * s + SIGMA_C * mu) / s;
        float ra1 = (ds   < 0.f) ? (-s   / ds)   : INFINITY;
        float ra2 = (dlam < 0.f) ? (-lam / dlam) : INFINITY;
        rat = fminf(ra1, ra2);
    }
#pragma unroll
    for (int o = 16; o > 0; o >>= 1) rat = fminf(rat, __shfl_down_sync(0xffffffffu, rat, o));
    if ((tid & 31) == 0) red[tid >> 5] = rat;
    __syncthreads();
    if (tid == 0) {
        float m = red[0];
        for (int wi = 1; wi < 12; wi++) m = fminf(m, red[wi]);
        salpha = fminf(1.f, 0.99f * m);
    }
    __syncthreads();
    float alpha = salpha;
    if (tid < NN) {
        g_z[t][tid]   = z   + alpha * dz;
        g_s[t][tid]   = s   + alpha * ds;
        g_lam[t][tid] = lam + alpha * dlam;
    }
    if (tid < NS) g_nu[t][tid] += alpha * rhs[tid];
}

// ---------------- W[t,w,d] = sum_n sup[t,n,d] * z[t,n*NW+w] ----------------
__global__ __launch_bounds__(256) void wproj_kernel(const float* __restrict__ sup) {
    int t = blockIdx.y;
    int d = blockIdx.x * 256 + threadIdx.x;
    __shared__ float zs[NN];
    for (int idx = threadIdx.x; idx < NN; idx += 256) zs[idx] = g_z[t][idx];
    __syncthreads();
    float acc[NW] = {0.f, 0.f, 0.f, 0.f, 0.f};
    const float* Sp = sup + (size_t)t * NS * DD + d;
    for (int n = 0; n < NS; n++) {
        float sv = Sp[(size_t)n * DD];
#pragma unroll
        for (int w = 0; w < NW; w++) acc[w] += sv * zs[n * NW + w];
    }
#pragma unroll
    for (int w = 0; w < NW; w++) g_W[t][w][d] = acc[w];
}

// ---------------- logits[t,q,w] = sum_d query[t,q,d] * W[t,w,d] ----------------
#define QT 10
__global__ __launch_bounds__(256) void logits_kernel(const float* __restrict__ query,
                                                     float* __restrict__ out) {
    int t = blockIdx.y;
    int q0 = blockIdx.x * QT;
    int tid = threadIdx.x;
    float acc[QT][NW];
#pragma unroll
    for (int q = 0; q < QT; q++)
#pragma unroll
        for (int w = 0; w < NW; w++) acc[q][w] = 0.f;
    const float* Qp = query + ((size_t)t * NQ + q0) * DD;
    for (int d = tid; d < DD; d += 256) {
        float wv[NW];
#pragma unroll
        for (int w = 0; w < NW; w++) wv[w] = g_W[t][w][d];
#pragma unroll
        for (int q = 0; q < QT; q++) {
            float qv = Qp[(size_t)q * DD + d];
#pragma unroll
            for (int w = 0; w < NW; w++) acc[q][w] += qv * wv[w];
        }
    }
#pragma unroll
    for (int q = 0; q < QT; q++)
#pragma unroll
        for (int w = 0; w < NW; w++)
#pragma unroll
            for (int o = 16; o > 0; o >>= 1)
                acc[q][w] += __shfl_down_sync(0xffffffffu, acc[q][w], o);
    __shared__ float part[8][QT * NW];
    int lane = tid & 31, warp = tid >> 5;
    if (lane == 0) {
#pragma unroll
        for (int q = 0; q < QT; q++)
#pragma unroll
            for (int w = 0; w < NW; w++) part[warp][q * NW + w] = acc[q][w];
    }
    __syncthreads();
    if (tid < QT * NW) {
        float v = 0.f;
#pragma unroll
        for (int wp = 0; wp < 8; wp++) v += part[wp][tid];
        int q = tid / NW, w = tid % NW;
        out[((size_t)t * NQ + q0 + q) * NW + w] = v;
    }
}

// ---------------- host ----------------
extern "C" void kernel_launch(void* const* d_in, const int* in_sizes, int n_in,
                              void* d_out, int out_size) {
    const float* query  = (const float*)d_in[0];
    const float* sup    = (const float*)d_in[1];
    const int*   labels = (const int*)d_in[2];
    (void)in_sizes; (void)n_in; (void)out_size;

    gram_kernel<<<dim3(4, T), 256>>>(sup);
    gram_reduce<<<(T * NS * NS + 255) / 256, 256>>>();
    setup_kernel<<<T, 384>>>(labels);
    for (int it = 0; it < MAXIT; it++) {
        resid_kernel<<<T, 384>>>();
        factor_kernel<<<dim3(NW, T), 256>>>();
        schur_kernel<<<T, 384>>>();
    }
    wproj_kernel<<<dim3(DD / 256, T), 256>>>(sup);
    logits_kernel<<<dim3(NQ / QT, T), 256>>>(query, (float*)d_out);
}